// round 16
// baseline (speedup 1.0000x reference)
#include <cuda_runtime.h>
#include <cuda_bf16.h>
#include <mma.h>

using namespace nvcuda;

#define NN 50000
#define DD 128
#define EE 600000
#define GG 512
#define LLAYERS 3
#define EDIM 16
#define JKD 384
#define ECHUNK 128
#define TROWS 128
#define NODE_T 512
#define NT128 ((NN + TROWS - 1) / TROWS)
#define WS 136   // bf16 smem stride (elems)
#define CS 136   // f32 staging stride (node)
#define AS 24    // attr bf16 stride
#define ES 132   // e_emb f32 stride

typedef unsigned long long u64;
typedef unsigned int u32;

// Scratch (device globals: no runtime allocation allowed)
__device__ float g_xcur[NN * DD];
__device__ float g_agg[NN * DD];           // zeroed by scatter_init / node each layer
__device__ float g_pool[GG * JKD];         // zeroed by head_kernel each call
__device__ int   g_cnt[NN];                // zeroed by k_scatter_init each call
__device__ int   g_cursor[NN];
__device__ int   g_csr_src[EE];
__device__ int   g_csr_dst[EE];
__device__ float g_csr_ea[(size_t)EE * EDIM];

__device__ __forceinline__ void red_v4(float* p, float4 v) {
    asm volatile("red.global.add.v4.f32 [%0], {%1,%2,%3,%4};"
                 :: "l"(p), "f"(v.x), "f"(v.y), "f"(v.z), "f"(v.w) : "memory");
}
__device__ __forceinline__ void red_v2(float* p, float x, float y) {
    asm volatile("red.global.add.v2.f32 [%0], {%1,%2};"
                 :: "l"(p), "f"(x), "f"(y) : "memory");
}

// ---------------------------------------------------------------------------
// CSR build. hist(1) -> scan(2) -> scatter_init(3) -> agg (#4, profiled).
// g_cnt zeroed by the PREVIOUS call's scatter_init (module-load zero, call 1).
// ---------------------------------------------------------------------------
__global__ void k_hist(const int* __restrict__ ei) {
    int e = blockIdx.x * blockDim.x + threadIdx.x;
    if (e < EE) atomicAdd(&g_cnt[ei[EE + e]], 1);
}

__global__ __launch_bounds__(1024) void k_scan_single() {
    __shared__ int s[1024];
    const int t = threadIdx.x;
    const int per = (NN + 1023) / 1024;
    const int base = t * per;
    int lim = NN - base;
    if (lim < 0) lim = 0;
    if (lim > per) lim = per;
    int loc = 0;
    for (int i = 0; i < lim; i++) loc += g_cnt[base + i];
    s[t] = loc;
    __syncthreads();
#pragma unroll
    for (int o = 1; o < 1024; o <<= 1) {
        int u = (t >= o) ? s[t - o] : 0;
        __syncthreads();
        s[t] += u;
        __syncthreads();
    }
    int run = (t > 0) ? s[t - 1] : 0;
    for (int i = 0; i < lim; i++) {
        const int c = g_cnt[base + i];
        g_cursor[base + i] = run;
        run += c;
    }
}

__global__ void k_scatter_init(const int* __restrict__ ei, const float* __restrict__ ea,
                               const float* __restrict__ x, const float* __restrict__ vn0) {
    int i = blockIdx.x * blockDim.x + threadIdx.x;
    if (i < EE) {
        const int dst = ei[EE + i];
        const int pos = atomicAdd(&g_cursor[dst], 1);
        g_csr_src[pos] = ei[i];
        g_csr_dst[pos] = dst;
        const float4* q = reinterpret_cast<const float4*>(&ea[(size_t)i * EDIM]);
        float4* s = reinterpret_cast<float4*>(&g_csr_ea[(size_t)pos * EDIM]);
        s[0] = q[0]; s[1] = q[1]; s[2] = q[2]; s[3] = q[3];
    }
    if (i < NN) g_cnt[i] = 0;
    if (i < NN * DD / 4) {
        float4 xv = reinterpret_cast<const float4*>(x)[i];
        float4 vv = reinterpret_cast<const float4*>(vn0)[i & 31];
        xv.x += vv.x; xv.y += vv.y; xv.z += vv.z; xv.w += vv.w;
        reinterpret_cast<float4*>(g_xcur)[i] = xv;
        reinterpret_cast<float4*>(g_agg)[i] = make_float4(0.f, 0.f, 0.f, 0.f);
    }
}

// ---------------------------------------------------------------------------
// Aggregation v2: per-CTA 128-edge chunks over the dst-sorted CSR stream.
//  1) stage attrs (bf16 hi/lo split) + src/dst into smem
//  2) WMMA encoder: e_emb[128x128] = attr @ We (3-pass split, f32 out -> smem)
//  3) scatter: warp-per-16-edge subrange; per edge just LDS.128 e_emb +
//     x[src] gather (2-deep pipeline) + add/relu/acc. Run-length flush:
//     first & last flush of each subrange RED.v4 (node may span subranges /
//     CTAs), interior nodes plain STG (sole owner).
// ---------------------------------------------------------------------------
__global__ __launch_bounds__(256, 2) void agg_wmma(
    const float* __restrict__ ew, const float* __restrict__ ebias)
{
    extern __shared__ __align__(32) char adyn[];
    __nv_bfloat16* sWh = reinterpret_cast<__nv_bfloat16*>(adyn);            // 16 x WS
    __nv_bfloat16* sWl = sWh + EDIM * WS;
    __nv_bfloat16* sAh = sWl + EDIM * WS;                                   // 128 x AS
    __nv_bfloat16* sAl = sAh + ECHUNK * AS;
    int2* sd = reinterpret_cast<int2*>(sAl + ECHUNK * AS);                  // 128
    float* sC = reinterpret_cast<float*>(sd + ECHUNK);                      // 128 x ES

    const int t = threadIdx.x;
    const int w = t >> 5;
    const int lane = t & 31;

    // encoder weights hi/lo (once)
    for (int idx = t; idx < EDIM * DD; idx += 256) {
        const int k = idx >> 7, n = idx & 127;
        const float v = ew[idx];
        const __nv_bfloat16 h = __float2bfloat16(v);
        sWh[k * WS + n] = h;
        sWl[k * WS + n] = __float2bfloat16(v - __bfloat162float(h));
    }
    const float4 bq = *reinterpret_cast<const float4*>(&ebias[lane * 4]);
    __syncthreads();

    const int epc = (EE + gridDim.x - 1) / gridDim.x;
    const int beg = blockIdx.x * epc;
    if (beg >= EE) return;
    const int end = (beg + epc < EE) ? beg + epc : EE;

    for (int cbeg = beg; cbeg < end; cbeg += ECHUNK) {
        const int cnt = ((end - cbeg) < ECHUNK) ? (end - cbeg) : ECHUNK;

        // ---- stage: attrs split hi/lo + sd ----
        for (int i = t; i < cnt * 4; i += 256) {   // float4 units (16 attrs = 4 f4)
            const float4 a4 =
                reinterpret_cast<const float4*>(&g_csr_ea[(size_t)cbeg * EDIM])[i];
            const int row = i >> 2, c4 = (i & 3) * 4;
            const float f[4] = {a4.x, a4.y, a4.z, a4.w};
#pragma unroll
            for (int j = 0; j < 4; j++) {
                const __nv_bfloat16 h = __float2bfloat16(f[j]);
                sAh[row * AS + c4 + j] = h;
                sAl[row * AS + c4 + j] = __float2bfloat16(f[j] - __bfloat162float(h));
            }
        }
        if (t < cnt) sd[t] = make_int2(g_csr_src[cbeg + t], g_csr_dst[cbeg + t]);
        __syncthreads();

        // ---- encode: warp w handles edge rows [16w, 16w+16) ----
        {
            wmma::fragment<wmma::accumulator, 16, 16, 16, float> acc[8];
#pragma unroll
            for (int j = 0; j < 8; j++) wmma::fill_fragment(acc[j], 0.f);
#pragma unroll
            for (int p = 0; p < 3; p++) {
                const __nv_bfloat16* As = (p == 2) ? sAl : sAh;
                const __nv_bfloat16* Bs = (p == 1) ? sWl : sWh;
                wmma::fragment<wmma::matrix_a, 16, 16, 16, __nv_bfloat16, wmma::row_major> af;
                wmma::load_matrix_sync(af, &As[w * 16 * AS], AS);
#pragma unroll
                for (int j = 0; j < 8; j++) {
                    wmma::fragment<wmma::matrix_b, 16, 16, 16, __nv_bfloat16, wmma::row_major> bf;
                    wmma::load_matrix_sync(bf, &Bs[j * 16], WS);
                    wmma::mma_sync(acc[j], af, bf, acc[j]);
                }
            }
#pragma unroll
            for (int j = 0; j < 8; j++)
                wmma::store_matrix_sync(&sC[w * 16 * ES + j * 16], acc[j], ES,
                                        wmma::mem_row_major);
        }
        __syncthreads();

        // ---- scatter: warp w owns local edges [16w, min(16w+16,cnt)) ----
        {
            const int s0 = 16 * w;
            const int s1 = (s0 + 16 < cnt) ? s0 + 16 : cnt;
            if (s0 < s1) {
                int2 e0 = sd[s0];
                int2 e1 = (s0 + 1 < s1) ? sd[s0 + 1] : e0;
                float4 x0 = *reinterpret_cast<const float4*>(
                    &g_xcur[(size_t)e0.x * DD + lane * 4]);
                float4 x1 = (s0 + 1 < s1)
                    ? *reinterpret_cast<const float4*>(
                          &g_xcur[(size_t)e1.x * DD + lane * 4]) : x0;

                float4 acc = make_float4(0.f, 0.f, 0.f, 0.f);
                int cur = e0.y;
                bool first = true;

                for (int i = s0; i < s1; i++) {
                    int2 e2 = e1;
                    float4 x2 = make_float4(0.f, 0.f, 0.f, 0.f);
                    if (i + 2 < s1) {
                        e2 = sd[i + 2];
                        x2 = *reinterpret_cast<const float4*>(
                            &g_xcur[(size_t)e2.x * DD + lane * 4]);
                    }

                    const float4 em =
                        *reinterpret_cast<const float4*>(&sC[i * ES + lane * 4]);
                    float4 m;
                    m.x = fmaxf(em.x + bq.x + x0.x, 0.f);
                    m.y = fmaxf(em.y + bq.y + x0.y, 0.f);
                    m.z = fmaxf(em.z + bq.z + x0.z, 0.f);
                    m.w = fmaxf(em.w + bq.w + x0.w, 0.f);

                    if (e0.y != cur) {   // warp-uniform
                        float* p = &g_agg[(size_t)cur * DD + lane * 4];
                        if (first) red_v4(p, acc);
                        else *reinterpret_cast<float4*>(p) = acc;
                        first = false;
                        acc = make_float4(0.f, 0.f, 0.f, 0.f);
                        cur = e0.y;
                    }
                    acc.x += m.x; acc.y += m.y; acc.z += m.z; acc.w += m.w;

                    x0 = x1; x1 = x2; e0 = e1; e1 = e2;
                }
                // last flush: node may continue into next subrange/CTA
                red_v4(&g_agg[(size_t)cur * DD + lane * 4], acc);
            }
        }
        __syncthreads();   // protect sA/sd/sC before next chunk
    }
}

// ---------------------------------------------------------------------------
// Node MLP on WMMA bf16 (R15 version — 761us best, unchanged)
// ---------------------------------------------------------------------------
__global__ __launch_bounds__(NODE_T, 1) void node_wmma(
    const float* __restrict__ w1, const float* __restrict__ b1,
    const float* __restrict__ w2, const float* __restrict__ b2,
    const float* __restrict__ epsp, const float* __restrict__ vn_next,
    const int* __restrict__ batch, int layer)
{
    extern __shared__ __align__(32) char dyn[];
    __nv_bfloat16* sW1h = reinterpret_cast<__nv_bfloat16*>(dyn);
    __nv_bfloat16* sW1l = sW1h + DD * WS;
    __nv_bfloat16* sW2h = sW1l + DD * WS;
    __nv_bfloat16* sW2l = sW2h + DD * WS;
    __nv_bfloat16* sAh  = sW2l + DD * WS;               // R region as A-hi
    __nv_bfloat16* sAl  = sAh + TROWS * WS;             // R region as A-lo
    float* sC = reinterpret_cast<float*>(sAh);          // R region as C (ALIAS)

    __shared__ float b1s[DD], b2s[DD];
    __shared__ int sB[TROWS];

    const int t = threadIdx.x;
    const int wid = t >> 5;

    for (int idx = t; idx < DD * DD; idx += NODE_T) {
        const int k = idx >> 7, n = idx & 127;
        float v = w1[idx];
        __nv_bfloat16 h = __float2bfloat16(v);
        sW1h[k * WS + n] = h;
        sW1l[k * WS + n] = __float2bfloat16(v - __bfloat162float(h));
        v = w2[idx];
        h = __float2bfloat16(v);
        sW2h[k * WS + n] = h;
        sW2l[k * WS + n] = __float2bfloat16(v - __bfloat162float(h));
    }
    if (t < DD) { b1s[t] = b1[t]; b2s[t] = b2[t]; }
    const float epsv = 1.0f + *epsp;

    const int r0 = (wid >> 1) * 16;
    const int c0 = (wid & 1) * 64;

    const int ccol = t & 127;
    const int crow0 = t >> 7;

    const int col2 = t & 63;
    const int seg = t >> 6;
    float2 vn2 = make_float2(0.f, 0.f);
    if (vn_next) vn2 = *reinterpret_cast<const float2*>(&vn_next[2 * col2]);
    const int zero_agg = (vn_next != nullptr);

    for (int tile = blockIdx.x; tile < NT128; tile += gridDim.x) {
        const int row0 = tile * TROWS;
        __syncthreads();

        for (int i = t; i < TROWS; i += NODE_T)
            sB[i] = (row0 + i < NN) ? batch[row0 + i] : -1;
        for (int i = t; i < TROWS * (DD / 4); i += NODE_T) {
            const int row = i >> 5, c4 = (i & 31) * 4;
            const int grow = row0 + row;
            float4 hv = make_float4(0.f, 0.f, 0.f, 0.f);
            if (grow < NN) {
                const int gi = row0 * (DD / 4) + i;
                const float4 xv = reinterpret_cast<const float4*>(g_xcur)[gi];
                const float4 av = reinterpret_cast<const float4*>(g_agg)[gi];
                hv.x = fmaf(epsv, xv.x, av.x);
                hv.y = fmaf(epsv, xv.y, av.y);
                hv.z = fmaf(epsv, xv.z, av.z);
                hv.w = fmaf(epsv, xv.w, av.w);
                if (zero_agg)
                    reinterpret_cast<float4*>(g_agg)[gi] = make_float4(0.f, 0.f, 0.f, 0.f);
            }
            __nv_bfloat16* ph = &sAh[row * WS + c4];
            __nv_bfloat16* pl = &sAl[row * WS + c4];
            const float f[4] = {hv.x, hv.y, hv.z, hv.w};
#pragma unroll
            for (int j = 0; j < 4; j++) {
                const __nv_bfloat16 hi = __float2bfloat16(f[j]);
                ph[j] = hi;
                pl[j] = __float2bfloat16(f[j] - __bfloat162float(hi));
            }
        }
        __syncthreads();

        wmma::fragment<wmma::accumulator, 16, 16, 16, float> acc[4];
#pragma unroll
        for (int j = 0; j < 4; j++) wmma::fill_fragment(acc[j], 0.f);
#pragma unroll
        for (int p = 0; p < 3; p++) {
            const __nv_bfloat16* As = (p == 2) ? sAl : sAh;
            const __nv_bfloat16* Bs = (p == 1) ? sW1l : sW1h;
            for (int k = 0; k < 8; k++) {
                wmma::fragment<wmma::matrix_a, 16, 16, 16, __nv_bfloat16, wmma::row_major> af;
                wmma::load_matrix_sync(af, &As[r0 * WS + k * 16], WS);
#pragma unroll
                for (int j = 0; j < 4; j++) {
                    wmma::fragment<wmma::matrix_b, 16, 16, 16, __nv_bfloat16, wmma::row_major> bf;
                    wmma::load_matrix_sync(bf, &Bs[k * 16 * WS + c0 + j * 16], WS);
                    wmma::mma_sync(acc[j], af, bf, acc[j]);
                }
            }
        }
        __syncthreads();
#pragma unroll
        for (int j = 0; j < 4; j++)
            wmma::store_matrix_sync(&sC[r0 * CS + c0 + j * 16], acc[j], CS,
                                    wmma::mem_row_major);
        __syncthreads();

        {
            float yreg[32];
#pragma unroll
            for (int j = 0; j < 32; j++) {
                const int row = crow0 + j * 4;
                yreg[j] = fmaxf(sC[row * CS + ccol] + b1s[ccol], 0.f);
            }
            __syncthreads();
#pragma unroll
            for (int j = 0; j < 32; j++) {
                const int row = crow0 + j * 4;
                const __nv_bfloat16 h = __float2bfloat16(yreg[j]);
                sAh[row * WS + ccol] = h;
                sAl[row * WS + ccol] = __float2bfloat16(yreg[j] - __bfloat162float(h));
            }
        }
        __syncthreads();

#pragma unroll
        for (int j = 0; j < 4; j++) wmma::fill_fragment(acc[j], 0.f);
#pragma unroll
        for (int p = 0; p < 3; p++) {
            const __nv_bfloat16* As = (p == 2) ? sAl : sAh;
            const __nv_bfloat16* Bs = (p == 1) ? sW2l : sW2h;
            for (int k = 0; k < 8; k++) {
                wmma::fragment<wmma::matrix_a, 16, 16, 16, __nv_bfloat16, wmma::row_major> af;
                wmma::load_matrix_sync(af, &As[r0 * WS + k * 16], WS);
#pragma unroll
                for (int j = 0; j < 4; j++) {
                    wmma::fragment<wmma::matrix_b, 16, 16, 16, __nv_bfloat16, wmma::row_major> bf;
                    wmma::load_matrix_sync(bf, &Bs[k * 16 * WS + c0 + j * 16], WS);
                    wmma::mma_sync(acc[j], af, bf, acc[j]);
                }
            }
        }
        __syncthreads();
#pragma unroll
        for (int j = 0; j < 4; j++)
            wmma::store_matrix_sync(&sC[r0 * CS + c0 + j * 16], acc[j], CS,
                                    wmma::mem_row_major);
        __syncthreads();

        {
            const float bx = b2s[2 * col2], by = b2s[2 * col2 + 1];
            float px = 0.f, py = 0.f;
            int curb = -1;
            for (int r = 0; r < 16; r++) {
                const int lrow = seg * 16 + r;
                const int grow = row0 + lrow;
                if (grow >= NN) break;
                const float vx = sC[lrow * CS + 2 * col2] + bx;
                const float vy = sC[lrow * CS + 2 * col2 + 1] + by;
                const int b = sB[lrow];
                if (b != curb) {
                    if (curb >= 0)
                        red_v2(&g_pool[curb * JKD + layer * DD + 2 * col2], px, py);
                    curb = b; px = 0.f; py = 0.f;
                }
                px += vx; py += vy;
                if (vn_next)
                    *reinterpret_cast<float2*>(&g_xcur[(size_t)grow * DD + 2 * col2]) =
                        make_float2(vx + vn2.x, vy + vn2.y);
            }
            if (curb >= 0)
                red_v2(&g_pool[curb * JKD + layer * DD + 2 * col2], px, py);
        }
    }
}

// ---------------------------------------------------------------------------
// Head (unchanged; re-zeroes g_pool rows for graph-replay determinism)
// ---------------------------------------------------------------------------
__device__ __forceinline__ float2 block_sum2(float a, float b) {
    __shared__ float2 sred[8];
    const int lane = threadIdx.x & 31, w = threadIdx.x >> 5;
#pragma unroll
    for (int o = 16; o; o >>= 1) {
        a += __shfl_down_sync(0xffffffffu, a, o);
        b += __shfl_down_sync(0xffffffffu, b, o);
    }
    if (lane == 0) sred[w] = make_float2(a, b);
    __syncthreads();
    if (w == 0) {
        float2 s = (lane < 8) ? sred[lane] : make_float2(0.f, 0.f);
#pragma unroll
        for (int o = 4; o; o >>= 1) {
            s.x += __shfl_down_sync(0xffffffffu, s.x, o);
            s.y += __shfl_down_sync(0xffffffffu, s.y, o);
        }
        if (lane == 0) sred[0] = s;
    }
    __syncthreads();
    const float2 r = sred[0];
    __syncthreads();
    return r;
}

__global__ __launch_bounds__(256) void head_kernel(
    const float* __restrict__ w1, const float* __restrict__ b1,
    const float* __restrict__ ga1, const float* __restrict__ be1,
    const float* __restrict__ w2, const float* __restrict__ b2,
    const float* __restrict__ ga2, const float* __restrict__ be2,
    const float* __restrict__ ow, const float* __restrict__ ob,
    float* __restrict__ out)
{
    __shared__ float sg[JKD];
    __shared__ float s1[256];
    const int g = blockIdx.x, t = threadIdx.x;

    for (int i = t; i < JKD; i += 256) {
        sg[i] = g_pool[g * JKD + i];
        g_pool[g * JKD + i] = 0.f;
    }
    __syncthreads();

    float acc = b1[t];
#pragma unroll 4
    for (int k = 0; k < JKD; k++) acc = fmaf(sg[k], w1[k * 256 + t], acc);
    float2 s = block_sum2(acc, acc * acc);
    float mu = s.x * (1.f / 256.f);
    float var = s.y * (1.f / 256.f) - mu * mu;
    s1[t] = fmaxf((acc - mu) * rsqrtf(var + 1e-5f) * ga1[t] + be1[t], 0.f);
    __syncthreads();

    float acc2 = 0.f;
    if (t < 128) {
        acc2 = b2[t];
#pragma unroll 4
        for (int k = 0; k < 256; k++) acc2 = fmaf(s1[k], w2[k * 128 + t], acc2);
    }
    const float cva = (t < 128) ? acc2 : 0.f;
    float2 s2 = block_sum2(cva, cva * cva);
    float mu2 = s2.x * (1.f / 128.f);
    float var2 = s2.y * (1.f / 128.f) - mu2 * mu2;
    float v2 = 0.f;
    if (t < 128) v2 = fmaxf((acc2 - mu2) * rsqrtf(var2 + 1e-5f) * ga2[t] + be2[t], 0.f);

    const float p = (t < 128) ? v2 * ow[t] : 0.f;
    float2 s3 = block_sum2(p, 0.f);
    if (t == 0) out[g] = s3.x + ob[0];
}

// ---------------------------------------------------------------------------
extern "C" void kernel_launch(void* const* d_in, const int* in_sizes, int n_in,
                              void* d_out, int out_size) {
    (void)in_sizes; (void)n_in; (void)out_size;
    const float* x     = (const float*)d_in[0];
    const int*   ei    = (const int*)d_in[1];
    const float* ea    = (const float*)d_in[2];
    const int*   batch = (const int*)d_in[3];
    const float* vn    = (const float*)d_in[4];
    const float* ew    = (const float*)d_in[5];
    const float* ebias = (const float*)d_in[6];
    const float* eps   = (const float*)d_in[7];
    const float* mw1   = (const float*)d_in[8];
    const float* mb1   = (const float*)d_in[9];
    const float* mw2   = (const float*)d_in[10];
    const float* mb2   = (const float*)d_in[11];
    const float* lw1   = (const float*)d_in[12];
    const float* lb1   = (const float*)d_in[13];
    const float* ln1g  = (const float*)d_in[14];
    const float* ln1b  = (const float*)d_in[15];
    const float* lw2   = (const float*)d_in[16];
    const float* lb2   = (const float*)d_in[17];
    const float* ln2g  = (const float*)d_in[18];
    const float* ln2b  = (const float*)d_in[19];
    const float* ow    = (const float*)d_in[20];
    const float* ob    = (const float*)d_in[21];
    float* out = (float*)d_out;

    int nsm = 148;
    cudaDeviceGetAttribute(&nsm, cudaDevAttrMultiProcessorCount, 0);

    const int node_smem = 4 * DD * WS * 2 + TROWS * WS * 2 * 2;   // 208896 B
    cudaFuncSetAttribute(node_wmma, cudaFuncAttributeMaxDynamicSharedMemorySize, node_smem);

    // agg smem: Wh/Wl (16xWS) + Ah/Al (128xAS) + sd + C (128xES f32)
    const int agg_smem = 2 * EDIM * WS * 2 + 2 * ECHUNK * AS * 2
                       + ECHUNK * 8 + ECHUNK * ES * 4;            // 89600 B
    cudaFuncSetAttribute(agg_wmma, cudaFuncAttributeMaxDynamicSharedMemorySize, agg_smem);

    k_hist<<<(EE + 255) / 256, 256>>>(ei);
    k_scan_single<<<1, 1024>>>();
    k_scatter_init<<<(NN * DD / 4 + 255) / 256, 256>>>(ei, ea, x, vn);

    for (int i = 0; i < LLAYERS; i++) {
        agg_wmma<<<nsm * 2, 256, agg_smem>>>(ew + i * EDIM * DD, ebias + i * DD);
        node_wmma<<<nsm, NODE_T, node_smem>>>(
            mw1 + i * DD * DD, mb1 + i * DD,
            mw2 + i * DD * DD, mb2 + i * DD,
            eps + i,
            (i < LLAYERS - 1) ? (vn + (i + 1) * DD) : nullptr,
            batch, i);
    }

    head_kernel<<<GG, 256>>>(lw1, lb1, ln1g, ln1b, lw2, lb2, ln2g, ln2b, ow, ob, out);
}

// round 17
// speedup vs baseline: 1.1388x; 1.1388x over previous
#include <cuda_runtime.h>
#include <cuda_bf16.h>
#include <mma.h>

using namespace nvcuda;

#define NN 50000
#define DD 128
#define EE 600000
#define GG 512
#define LLAYERS 3
#define EDIM 16
#define JKD 384
#define CHUNK 32
#define TROWS 128
#define NODE_T 512
#define NT128 ((NN + TROWS - 1) / TROWS)
#define WS 136   // bf16 smem stride (elems)
#define CS 136   // f32 staging stride

typedef unsigned long long u64;
typedef unsigned int u32;

// Scratch (device globals: no runtime allocation allowed)
__device__ float g_xcur[NN * DD];
__device__ float g_agg[NN * DD];           // zeroed by scatter_init / node each layer
__device__ float g_pool[GG * JKD];         // zeroed by head_kernel each call
__device__ int   g_cnt[NN];                // zeroed by k_scatter_init each call
__device__ int   g_cursor[NN];
__device__ int   g_csr_src[EE];
__device__ int   g_csr_dst[EE];
__device__ float g_csr_ea[(size_t)EE * EDIM];

// ---------------------------------------------------------------------------
// packed f32x2 helpers
// ---------------------------------------------------------------------------
__device__ __forceinline__ u64 pack2(float x, float y) {
    u64 r; asm("mov.b64 %0, {%1, %2};" : "=l"(r) : "f"(x), "f"(y)); return r;
}
__device__ __forceinline__ float2 unpack2(u64 v) {
    float2 r; asm("mov.b64 {%0, %1}, %2;" : "=f"(r.x), "=f"(r.y) : "l"(v)); return r;
}
__device__ __forceinline__ void fma2(u64& d, u64 a, u64 b) {
    asm("fma.rn.f32x2 %0, %1, %2, %0;" : "+l"(d) : "l"(a), "l"(b));
}
__device__ __forceinline__ void red_v4(float* p, float4 v) {
    asm volatile("red.global.add.v4.f32 [%0], {%1,%2,%3,%4};"
                 :: "l"(p), "f"(v.x), "f"(v.y), "f"(v.z), "f"(v.w) : "memory");
}
__device__ __forceinline__ void red_v2(float* p, float x, float y) {
    asm volatile("red.global.add.v2.f32 [%0], {%1,%2};"
                 :: "l"(p), "f"(x), "f"(y) : "memory");
}

// ---------------------------------------------------------------------------
// CSR build. hist(1) -> scan(2) -> scatter_init(3) -> agg (#4, profiled).
// g_cnt zeroed by the PREVIOUS call's scatter_init (module-load zero, call 1).
// ---------------------------------------------------------------------------
__global__ void k_hist(const int* __restrict__ ei) {
    int e = blockIdx.x * blockDim.x + threadIdx.x;
    if (e < EE) atomicAdd(&g_cnt[ei[EE + e]], 1);
}

__global__ __launch_bounds__(1024) void k_scan_single() {
    __shared__ int s[1024];
    const int t = threadIdx.x;
    const int per = (NN + 1023) / 1024;
    const int base = t * per;
    int lim = NN - base;
    if (lim < 0) lim = 0;
    if (lim > per) lim = per;
    int loc = 0;
    for (int i = 0; i < lim; i++) loc += g_cnt[base + i];
    s[t] = loc;
    __syncthreads();
#pragma unroll
    for (int o = 1; o < 1024; o <<= 1) {
        int u = (t >= o) ? s[t - o] : 0;
        __syncthreads();
        s[t] += u;
        __syncthreads();
    }
    int run = (t > 0) ? s[t - 1] : 0;
    for (int i = 0; i < lim; i++) {
        const int c = g_cnt[base + i];
        g_cursor[base + i] = run;
        run += c;
    }
}

__global__ void k_scatter_init(const int* __restrict__ ei, const float* __restrict__ ea,
                               const float* __restrict__ x, const float* __restrict__ vn0) {
    int i = blockIdx.x * blockDim.x + threadIdx.x;
    if (i < EE) {
        const int dst = ei[EE + i];
        const int pos = atomicAdd(&g_cursor[dst], 1);
        g_csr_src[pos] = ei[i];
        g_csr_dst[pos] = dst;
        const float4* q = reinterpret_cast<const float4*>(&ea[(size_t)i * EDIM]);
        float4* s = reinterpret_cast<float4*>(&g_csr_ea[(size_t)pos * EDIM]);
        s[0] = q[0]; s[1] = q[1]; s[2] = q[2]; s[3] = q[3];
    }
    if (i < NN) g_cnt[i] = 0;
    if (i < NN * DD / 4) {
        float4 xv = reinterpret_cast<const float4*>(x)[i];
        float4 vv = reinterpret_cast<const float4*>(vn0)[i & 31];
        xv.x += vv.x; xv.y += vv.y; xv.z += vv.z; xv.w += vv.w;
        reinterpret_cast<float4*>(g_xcur)[i] = xv;
        reinterpret_cast<float4*>(g_agg)[i] = make_float4(0.f, 0.f, 0.f, 0.f);
    }
}

// ---------------------------------------------------------------------------
// Aggregation (scalar R8/R15 version, 101.5us measured 5x) with ONE change:
// unroll-2 on the scatter inner loop so ptxas renames the software-pipeline
// registers (x0<-x1<-x2, sd shifts) instead of emitting ~12 MOVs per edge.
// ---------------------------------------------------------------------------
__global__ __launch_bounds__(256, 2) void agg_kernel(
    const float* __restrict__ ew, const float* __restrict__ ebias)
{
    __shared__ float s_attr[8][2][CHUNK * EDIM];
    __shared__ int2  s_sd[8][2][CHUNK];

    const int lane = threadIdx.x & 31;
    const int w = threadIdx.x >> 5;

    u64 wp[8][4];
#pragma unroll
    for (int j = 0; j < 8; j++)
#pragma unroll
        for (int c = 0; c < 4; c++)
            wp[j][c] = pack2(ew[(2 * j) * DD + lane * 4 + c],
                             ew[(2 * j + 1) * DD + lane * 4 + c]);
    const float4 bq = *reinterpret_cast<const float4*>(&ebias[lane * 4]);

    const int warp = (blockIdx.x * blockDim.x + threadIdx.x) >> 5;
    const int nw = (gridDim.x * blockDim.x) >> 5;
    const int epw = (EE + nw - 1) / nw;
    const int beg = warp * epw;
    if (beg >= EE) return;
    const int range = ((beg + epw < EE) ? beg + epw : EE) - beg;
    const int nchunks = (range + CHUNK - 1) / CHUNK;

    {
        const int cnt = (range < CHUNK) ? range : CHUNK;
        const float4* src4 = reinterpret_cast<const float4*>(&g_csr_ea[(size_t)beg * EDIM]);
        float4* dst4 = reinterpret_cast<float4*>(&s_attr[w][0][0]);
        for (int i = lane; i < cnt * 4; i += 32) dst4[i] = src4[i];
        if (lane < cnt) s_sd[w][0][lane] = make_int2(g_csr_src[beg + lane], g_csr_dst[beg + lane]);
    }
    __syncwarp();

    int2 sd0 = s_sd[w][0][0];
    int2 sd1 = (range > 1) ? s_sd[w][0][1] : sd0;
    float4 x0 = *reinterpret_cast<const float4*>(&g_xcur[(size_t)sd0.x * DD + lane * 4]);
    float4 x1 = (range > 1)
        ? *reinterpret_cast<const float4*>(&g_xcur[(size_t)sd1.x * DD + lane * 4]) : x0;

    float4 acc = make_float4(0.f, 0.f, 0.f, 0.f);
    int cur = sd0.y;
    bool firstflush = true;
    int gpos = 0;
    int buf = 0;

    for (int c = 0; c < nchunks; c++) {
        const int cbeg = c * CHUNK;
        const int cnt = ((range - cbeg) < CHUNK) ? (range - cbeg) : CHUNK;

        __syncwarp();
        if (c + 1 < nchunks) {
            const int nbeg = beg + cbeg + CHUNK;
            const int ncnt = ((range - cbeg - CHUNK) < CHUNK) ? (range - cbeg - CHUNK) : CHUNK;
            const float4* src4 = reinterpret_cast<const float4*>(&g_csr_ea[(size_t)nbeg * EDIM]);
            float4* dst4 = reinterpret_cast<float4*>(&s_attr[w][buf ^ 1][0]);
            for (int i = lane; i < ncnt * 4; i += 32) dst4[i] = src4[i];
            if (lane < ncnt)
                s_sd[w][buf ^ 1][lane] = make_int2(g_csr_src[nbeg + lane], g_csr_dst[nbeg + lane]);
        }
        __syncwarp();

#pragma unroll 2
        for (int i = 0; i < cnt; i++) {
            int2 sd2 = sd1;
            float4 x2 = make_float4(0.f, 0.f, 0.f, 0.f);
            if (gpos + 2 < range) {
                const int ii = i + 2;
                sd2 = (ii < cnt) ? s_sd[w][buf][ii] : s_sd[w][buf ^ 1][ii - cnt];
                x2 = *reinterpret_cast<const float4*>(&g_xcur[(size_t)sd2.x * DD + lane * 4]);
            }

            const u64* ap = reinterpret_cast<const u64*>(&s_attr[w][buf][i * EDIM]);
            u64 ac0 = pack2(bq.x, 0.f), ac1 = pack2(bq.y, 0.f);
            u64 ac2 = pack2(bq.z, 0.f), ac3 = pack2(bq.w, 0.f);
#pragma unroll
            for (int j = 0; j < 8; j++) {
                const u64 aj = ap[j];
                fma2(ac0, aj, wp[j][0]);
                fma2(ac1, aj, wp[j][1]);
                fma2(ac2, aj, wp[j][2]);
                fma2(ac3, aj, wp[j][3]);
            }
            const float2 q0 = unpack2(ac0), q1 = unpack2(ac1);
            const float2 q2 = unpack2(ac2), q3 = unpack2(ac3);
            const float m0 = fmaxf(q0.x + q0.y + x0.x, 0.f);
            const float m1 = fmaxf(q1.x + q1.y + x0.y, 0.f);
            const float m2 = fmaxf(q2.x + q2.y + x0.z, 0.f);
            const float m3 = fmaxf(q3.x + q3.y + x0.w, 0.f);

            if (sd0.y != cur) {
                float* p = &g_agg[(size_t)cur * DD + lane * 4];
                if (firstflush) red_v4(p, acc);
                else *reinterpret_cast<float4*>(p) = acc;
                firstflush = false;
                acc = make_float4(0.f, 0.f, 0.f, 0.f);
                cur = sd0.y;
            }
            acc.x += m0; acc.y += m1; acc.z += m2; acc.w += m3;

            x0 = x1; x1 = x2; sd0 = sd1; sd1 = sd2; gpos++;
        }
        buf ^= 1;
    }
    red_v4(&g_agg[(size_t)cur * DD + lane * 4], acc);
}

// ---------------------------------------------------------------------------
// Node MLP on WMMA bf16 (R15 version — 761us best, unchanged):
//  512 threads (16 warps), 128-row tiles, GEMM acc in registers,
//  f32 C staging ALIASES the bf16 A hi/lo region.
// ---------------------------------------------------------------------------
__global__ __launch_bounds__(NODE_T, 1) void node_wmma(
    const float* __restrict__ w1, const float* __restrict__ b1,
    const float* __restrict__ w2, const float* __restrict__ b2,
    const float* __restrict__ epsp, const float* __restrict__ vn_next,
    const int* __restrict__ batch, int layer)
{
    extern __shared__ __align__(32) char dyn[];
    __nv_bfloat16* sW1h = reinterpret_cast<__nv_bfloat16*>(dyn);
    __nv_bfloat16* sW1l = sW1h + DD * WS;
    __nv_bfloat16* sW2h = sW1l + DD * WS;
    __nv_bfloat16* sW2l = sW2h + DD * WS;
    __nv_bfloat16* sAh  = sW2l + DD * WS;               // R region as A-hi
    __nv_bfloat16* sAl  = sAh + TROWS * WS;             // R region as A-lo
    float* sC = reinterpret_cast<float*>(sAh);          // R region as C (ALIAS)

    __shared__ float b1s[DD], b2s[DD];
    __shared__ int sB[TROWS];

    const int t = threadIdx.x;
    const int wid = t >> 5;

    for (int idx = t; idx < DD * DD; idx += NODE_T) {
        const int k = idx >> 7, n = idx & 127;
        float v = w1[idx];
        __nv_bfloat16 h = __float2bfloat16(v);
        sW1h[k * WS + n] = h;
        sW1l[k * WS + n] = __float2bfloat16(v - __bfloat162float(h));
        v = w2[idx];
        h = __float2bfloat16(v);
        sW2h[k * WS + n] = h;
        sW2l[k * WS + n] = __float2bfloat16(v - __bfloat162float(h));
    }
    if (t < DD) { b1s[t] = b1[t]; b2s[t] = b2[t]; }
    const float epsv = 1.0f + *epsp;

    const int r0 = (wid >> 1) * 16;
    const int c0 = (wid & 1) * 64;

    const int ccol = t & 127;
    const int crow0 = t >> 7;

    const int col2 = t & 63;
    const int seg = t >> 6;
    float2 vn2 = make_float2(0.f, 0.f);
    if (vn_next) vn2 = *reinterpret_cast<const float2*>(&vn_next[2 * col2]);
    const int zero_agg = (vn_next != nullptr);

    for (int tile = blockIdx.x; tile < NT128; tile += gridDim.x) {
        const int row0 = tile * TROWS;
        __syncthreads();

        for (int i = t; i < TROWS; i += NODE_T)
            sB[i] = (row0 + i < NN) ? batch[row0 + i] : -1;
        for (int i = t; i < TROWS * (DD / 4); i += NODE_T) {
            const int row = i >> 5, c4 = (i & 31) * 4;
            const int grow = row0 + row;
            float4 hv = make_float4(0.f, 0.f, 0.f, 0.f);
            if (grow < NN) {
                const int gi = row0 * (DD / 4) + i;
                const float4 xv = reinterpret_cast<const float4*>(g_xcur)[gi];
                const float4 av = reinterpret_cast<const float4*>(g_agg)[gi];
                hv.x = fmaf(epsv, xv.x, av.x);
                hv.y = fmaf(epsv, xv.y, av.y);
                hv.z = fmaf(epsv, xv.z, av.z);
                hv.w = fmaf(epsv, xv.w, av.w);
                if (zero_agg)
                    reinterpret_cast<float4*>(g_agg)[gi] = make_float4(0.f, 0.f, 0.f, 0.f);
            }
            __nv_bfloat16* ph = &sAh[row * WS + c4];
            __nv_bfloat16* pl = &sAl[row * WS + c4];
            const float f[4] = {hv.x, hv.y, hv.z, hv.w};
#pragma unroll
            for (int j = 0; j < 4; j++) {
                const __nv_bfloat16 hi = __float2bfloat16(f[j]);
                ph[j] = hi;
                pl[j] = __float2bfloat16(f[j] - __bfloat162float(hi));
            }
        }
        __syncthreads();

        wmma::fragment<wmma::accumulator, 16, 16, 16, float> acc[4];
#pragma unroll
        for (int j = 0; j < 4; j++) wmma::fill_fragment(acc[j], 0.f);
#pragma unroll
        for (int p = 0; p < 3; p++) {
            const __nv_bfloat16* As = (p == 2) ? sAl : sAh;
            const __nv_bfloat16* Bs = (p == 1) ? sW1l : sW1h;
            for (int k = 0; k < 8; k++) {
                wmma::fragment<wmma::matrix_a, 16, 16, 16, __nv_bfloat16, wmma::row_major> af;
                wmma::load_matrix_sync(af, &As[r0 * WS + k * 16], WS);
#pragma unroll
                for (int j = 0; j < 4; j++) {
                    wmma::fragment<wmma::matrix_b, 16, 16, 16, __nv_bfloat16, wmma::row_major> bf;
                    wmma::load_matrix_sync(bf, &Bs[k * 16 * WS + c0 + j * 16], WS);
                    wmma::mma_sync(acc[j], af, bf, acc[j]);
                }
            }
        }
        __syncthreads();
#pragma unroll
        for (int j = 0; j < 4; j++)
            wmma::store_matrix_sync(&sC[r0 * CS + c0 + j * 16], acc[j], CS,
                                    wmma::mem_row_major);
        __syncthreads();

        {
            float yreg[32];
#pragma unroll
            for (int j = 0; j < 32; j++) {
                const int row = crow0 + j * 4;
                yreg[j] = fmaxf(sC[row * CS + ccol] + b1s[ccol], 0.f);
            }
            __syncthreads();
#pragma unroll
            for (int j = 0; j < 32; j++) {
                const int row = crow0 + j * 4;
                const __nv_bfloat16 h = __float2bfloat16(yreg[j]);
                sAh[row * WS + ccol] = h;
                sAl[row * WS + ccol] = __float2bfloat16(yreg[j] - __bfloat162float(h));
            }
        }
        __syncthreads();

#pragma unroll
        for (int j = 0; j < 4; j++) wmma::fill_fragment(acc[j], 0.f);
#pragma unroll
        for (int p = 0; p < 3; p++) {
            const __nv_bfloat16* As = (p == 2) ? sAl : sAh;
            const __nv_bfloat16* Bs = (p == 1) ? sW2l : sW2h;
            for (int k = 0; k < 8; k++) {
                wmma::fragment<wmma::matrix_a, 16, 16, 16, __nv_bfloat16, wmma::row_major> af;
                wmma::load_matrix_sync(af, &As[r0 * WS + k * 16], WS);
#pragma unroll
                for (int j = 0; j < 4; j++) {
                    wmma::fragment<wmma::matrix_b, 16, 16, 16, __nv_bfloat16, wmma::row_major> bf;
                    wmma::load_matrix_sync(bf, &Bs[k * 16 * WS + c0 + j * 16], WS);
                    wmma::mma_sync(acc[j], af, bf, acc[j]);
                }
            }
        }
        __syncthreads();
#pragma unroll
        for (int j = 0; j < 4; j++)
            wmma::store_matrix_sync(&sC[r0 * CS + c0 + j * 16], acc[j], CS,
                                    wmma::mem_row_major);
        __syncthreads();

        {
            const float bx = b2s[2 * col2], by = b2s[2 * col2 + 1];
            float px = 0.f, py = 0.f;
            int curb = -1;
            for (int r = 0; r < 16; r++) {
                const int lrow = seg * 16 + r;
                const int grow = row0 + lrow;
                if (grow >= NN) break;
                const float vx = sC[lrow * CS + 2 * col2] + bx;
                const float vy = sC[lrow * CS + 2 * col2 + 1] + by;
                const int b = sB[lrow];
                if (b != curb) {
                    if (curb >= 0)
                        red_v2(&g_pool[curb * JKD + layer * DD + 2 * col2], px, py);
                    curb = b; px = 0.f; py = 0.f;
                }
                px += vx; py += vy;
                if (vn_next)
                    *reinterpret_cast<float2*>(&g_xcur[(size_t)grow * DD + 2 * col2]) =
                        make_float2(vx + vn2.x, vy + vn2.y);
            }
            if (curb >= 0)
                red_v2(&g_pool[curb * JKD + layer * DD + 2 * col2], px, py);
        }
    }
}

// ---------------------------------------------------------------------------
// Head (unchanged; re-zeroes g_pool rows for graph-replay determinism)
// ---------------------------------------------------------------------------
__device__ __forceinline__ float2 block_sum2(float a, float b) {
    __shared__ float2 sred[8];
    const int lane = threadIdx.x & 31, w = threadIdx.x >> 5;
#pragma unroll
    for (int o = 16; o; o >>= 1) {
        a += __shfl_down_sync(0xffffffffu, a, o);
        b += __shfl_down_sync(0xffffffffu, b, o);
    }
    if (lane == 0) sred[w] = make_float2(a, b);
    __syncthreads();
    if (w == 0) {
        float2 s = (lane < 8) ? sred[lane] : make_float2(0.f, 0.f);
#pragma unroll
        for (int o = 4; o; o >>= 1) {
            s.x += __shfl_down_sync(0xffffffffu, s.x, o);
            s.y += __shfl_down_sync(0xffffffffu, s.y, o);
        }
        if (lane == 0) sred[0] = s;
    }
    __syncthreads();
    const float2 r = sred[0];
    __syncthreads();
    return r;
}

__global__ __launch_bounds__(256) void head_kernel(
    const float* __restrict__ w1, const float* __restrict__ b1,
    const float* __restrict__ ga1, const float* __restrict__ be1,
    const float* __restrict__ w2, const float* __restrict__ b2,
    const float* __restrict__ ga2, const float* __restrict__ be2,
    const float* __restrict__ ow, const float* __restrict__ ob,
    float* __restrict__ out)
{
    __shared__ float sg[JKD];
    __shared__ float s1[256];
    const int g = blockIdx.x, t = threadIdx.x;

    for (int i = t; i < JKD; i += 256) {
        sg[i] = g_pool[g * JKD + i];
        g_pool[g * JKD + i] = 0.f;
    }
    __syncthreads();

    float acc = b1[t];
#pragma unroll 4
    for (int k = 0; k < JKD; k++) acc = fmaf(sg[k], w1[k * 256 + t], acc);
    float2 s = block_sum2(acc, acc * acc);
    float mu = s.x * (1.f / 256.f);
    float var = s.y * (1.f / 256.f) - mu * mu;
    s1[t] = fmaxf((acc - mu) * rsqrtf(var + 1e-5f) * ga1[t] + be1[t], 0.f);
    __syncthreads();

    float acc2 = 0.f;
    if (t < 128) {
        acc2 = b2[t];
#pragma unroll 4
        for (int k = 0; k < 256; k++) acc2 = fmaf(s1[k], w2[k * 128 + t], acc2);
    }
    const float cva = (t < 128) ? acc2 : 0.f;
    float2 s2 = block_sum2(cva, cva * cva);
    float mu2 = s2.x * (1.f / 128.f);
    float var2 = s2.y * (1.f / 128.f) - mu2 * mu2;
    float v2 = 0.f;
    if (t < 128) v2 = fmaxf((acc2 - mu2) * rsqrtf(var2 + 1e-5f) * ga2[t] + be2[t], 0.f);

    const float p = (t < 128) ? v2 * ow[t] : 0.f;
    float2 s3 = block_sum2(p, 0.f);
    if (t == 0) out[g] = s3.x + ob[0];
}

// ---------------------------------------------------------------------------
extern "C" void kernel_launch(void* const* d_in, const int* in_sizes, int n_in,
                              void* d_out, int out_size) {
    (void)in_sizes; (void)n_in; (void)out_size;
    const float* x     = (const float*)d_in[0];
    const int*   ei    = (const int*)d_in[1];
    const float* ea    = (const float*)d_in[2];
    const int*   batch = (const int*)d_in[3];
    const float* vn    = (const float*)d_in[4];
    const float* ew    = (const float*)d_in[5];
    const float* ebias = (const float*)d_in[6];
    const float* eps   = (const float*)d_in[7];
    const float* mw1   = (const float*)d_in[8];
    const float* mb1   = (const float*)d_in[9];
    const float* mw2   = (const float*)d_in[10];
    const float* mb2   = (const float*)d_in[11];
    const float* lw1   = (const float*)d_in[12];
    const float* lb1   = (const float*)d_in[13];
    const float* ln1g  = (const float*)d_in[14];
    const float* ln1b  = (const float*)d_in[15];
    const float* lw2   = (const float*)d_in[16];
    const float* lb2   = (const float*)d_in[17];
    const float* ln2g  = (const float*)d_in[18];
    const float* ln2b  = (const float*)d_in[19];
    const float* ow    = (const float*)d_in[20];
    const float* ob    = (const float*)d_in[21];
    float* out = (float*)d_out;

    int nsm = 148;
    cudaDeviceGetAttribute(&nsm, cudaDevAttrMultiProcessorCount, 0);

    const int node_smem = 4 * DD * WS * 2 + TROWS * WS * 2 * 2;   // 208896 B
    cudaFuncSetAttribute(node_wmma, cudaFuncAttributeMaxDynamicSharedMemorySize, node_smem);

    k_hist<<<(EE + 255) / 256, 256>>>(ei);
    k_scan_single<<<1, 1024>>>();
    k_scatter_init<<<(NN * DD / 4 + 255) / 256, 256>>>(ei, ea, x, vn);

    for (int i = 0; i < LLAYERS; i++) {
        agg_kernel<<<nsm * 2, 256>>>(ew + i * EDIM * DD, ebias + i * DD);
        node_wmma<<<nsm, NODE_T, node_smem>>>(
            mw1 + i * DD * DD, mb1 + i * DD,
            mw2 + i * DD * DD, mb2 + i * DD,
            eps + i,
            (i < LLAYERS - 1) ? (vn + (i + 1) * DD) : nullptr,
            batch, i);
    }

    head_kernel<<<GG, 256>>>(lw1, lb1, ln1g, ln1b, lw2, lb2, ln2g, ln2b, ow, ob, out);
}